// round 17
// baseline (speedup 1.0000x reference)
#include <cuda_runtime.h>
#include <cuda_fp16.h>
#include <cstdint>

#define N_NODES 100000
#define N_EDGES 1600000
#define D 128
#define CAP 128                 // bucket capacity (Poisson(16): P(>=128)~1e-60)

#define NT_TILES 782            // ceil(100000/128)
#define GRID_GEMM 148

// ---------------- scratch (device globals; no allocation) -------------------
__device__ __half   g_xh[N_NODES * D];
__device__ uint32_t g_wp[64 * 128];         // W pair-packed half2
__device__ uint32_t g_rp[64 * 128];         // R pair-packed half2
__device__ int g_cnt[N_NODES];
__device__ int g_csr[N_NODES * CAP];
__device__ int g_is64;

__device__ __forceinline__ void cp16(void* dst, const void* src) {
    uint32_t d = (uint32_t)__cvta_generic_to_shared(dst);
    asm volatile("cp.async.cg.shared.global [%0], [%1], 16;" :: "r"(d), "l"(src));
}
__device__ __forceinline__ uint32_t packh2(float a, float b) {
    __half2 h = __floats2half2_rn(a, b);
    return *reinterpret_cast<uint32_t*>(&h);
}

// ---------------------------------------------------------------------------
__global__ void detect_zero_kernel(const int* __restrict__ ei32) {
    int i = blockIdx.x * blockDim.x + threadIdx.x;
    if (i == 0) {
        int allzero = 1;
        for (int k = 0; k < 64; k++)
            if (ei32[2 * k + 1] != 0) { allzero = 0; break; }
        g_is64 = allzero;
    }
    if (i < N_NODES) g_cnt[i] = 0;
}

// merged prep: even blocks fill buckets, odd blocks convert x, last block cvt W/R
__global__ void prep_kernel(const float* __restrict__ x,
                            const float* __restrict__ W,
                            const float* __restrict__ R,
                            const void* __restrict__ ei_raw) {
    const int b = blockIdx.x;
    const int t = threadIdx.x;

    if (b == 12500) {
        for (int i = t; i < 64 * 128; i += 256) {
            int kp = i >> 7, n = i & 127;
            g_wp[i] = packh2(W[(2 * kp) * 128 + n], W[(2 * kp + 1) * 128 + n]);
            g_rp[i] = packh2(R[(2 * kp) * 128 + n], R[(2 * kp + 1) * 128 + n]);
        }
        return;
    }

    if ((b & 1) == 0) {           // fill
        int e = (b >> 1) * 256 + t;
        if (e >= N_EDGES) return;
        long long row, col;
        if (g_is64) {
            const long long* ei = (const long long*)ei_raw;
            row = ei[e]; col = ei[N_EDGES + e];
        } else {
            const int* ei = (const int*)ei_raw;
            row = ei[e]; col = ei[N_EDGES + e];
        }
        if ((unsigned long long)row >= N_NODES || (unsigned long long)col >= N_NODES)
            return;
        int p = atomicAdd(g_cnt + (int)row, 1);
        if (p < CAP) g_csr[(int)row * CAP + p] = (int)col;
    } else {                      // cvt x
        int i = (b >> 1) * 256 + t;
        const int tot = N_NODES * D / 8;
        if (i >= tot) return;
        const float4 v0 = __ldg((const float4*)(x + i * 8));
        const float4 v1 = __ldg((const float4*)(x + i * 8 + 4));
        uint4 o;
        o.x = packh2(v0.x, v0.y); o.y = packh2(v0.z, v0.w);
        o.z = packh2(v1.x, v1.y); o.w = packh2(v1.z, v1.w);
        *reinterpret_cast<uint4*>(g_xh + i * 8) = o;
    }
}

// ---------------------------------------------------------------------------
// Persistent fused aggregate+GEMM: 148 CTAs x 512 thr, 128-row tiles.
// out = x @ R + (invd*sum_nbr x) @ W + bias (mma.m16n8k16, fp32 accum).
// B resident; xA double-buffered via cp.async; aggA double-buffered via
// in-kernel CSR gather (warp w gathers rows w*8..w*8+7 of NEXT tile while
// other-parity warps run MMA of current tile).
// SMEM: xA[2][128*AP]h | aggA[2][128*AP]h | BR | BW = 208,896 B
// ---------------------------------------------------------------------------
#define AP 136
#define BP 136
#define ABUF_B   (128 * AP * 2)            // 34,816 B
#define XA_B(bf)  ((bf) * ABUF_B)
#define AGG_B(bf) (2 * ABUF_B + (bf) * ABUF_B)
#define BR_B      (4 * ABUF_B)
#define BW_B      (BR_B + 64 * BP * 4)
#define SM_BYTES  (BW_B + 64 * BP * 4)     // 208,896

__global__ __launch_bounds__(512, 1) void gemm_fused(
    const float* __restrict__ bias, float* __restrict__ out) {
    extern __shared__ char smraw[];
    uint32_t* BR = (uint32_t*)(smraw + BR_B);
    uint32_t* BW = (uint32_t*)(smraw + BW_B);

    const int t = threadIdx.x;
    const int wid = t >> 5;
    const int lane = t & 31;
    const int wm = wid >> 2;
    const int wn = wid & 3;
    const int lr = lane >> 2;
    const int lk = lane & 3;
    const int lq = lane & 3;
    const int arow = wm * 32 + lr;
    const int bn = wn * 32 + lr;

    auto load_xA = [&](int tile, int bf) {
        const int row0 = tile * 128;
        __half* xA = (__half*)(smraw + XA_B(bf));
#pragma unroll
        for (int v = t; v < 2048; v += 512) {
            int r = v >> 4;
            int c8 = (v & 15) << 3;
            int gr = row0 + r; if (gr >= N_NODES) gr = N_NODES - 1;
            cp16((char*)xA + r * AP * 2 + c8 * 2, g_xh + (long long)gr * D + c8);
        }
    };

    // CSR gather of one tile's agg rows into smem buffer (warp w -> 8 rows)
    auto gather_agg = [&](int tile, int bf) {
        __half* aggA = (__half*)(smraw + AGG_B(bf));
        const int row0 = tile * 128;
#pragma unroll 1
        for (int i = 0; i < 8; i++) {
            const int nl = wid * 8 + i;
            const int n = row0 + nl;
            if (n >= N_NODES) continue;   // stale smem harmless: rows never stored
            const int base = n * CAP;
            const int cnt = g_cnt[n];
            const int m = min(cnt, CAP);
            float4 acc = make_float4(0.f, 0.f, 0.f, 0.f);
            int j = 0;
            for (; j + 4 <= m; j += 4) {
                int c0 = g_csr[base + j];
                int c1 = g_csr[base + j + 1];
                int c2 = g_csr[base + j + 2];
                int c3 = g_csr[base + j + 3];
                uint2 u0 = __ldg((const uint2*)(g_xh + (long long)c0 * D + lane * 4));
                uint2 u1 = __ldg((const uint2*)(g_xh + (long long)c1 * D + lane * 4));
                uint2 u2 = __ldg((const uint2*)(g_xh + (long long)c2 * D + lane * 4));
                uint2 u3 = __ldg((const uint2*)(g_xh + (long long)c3 * D + lane * 4));
#pragma unroll
                for (int q = 0; q < 4; q++) {
                    uint2 u = q == 0 ? u0 : q == 1 ? u1 : q == 2 ? u2 : u3;
                    float2 f0 = __half22float2(*reinterpret_cast<__half2*>(&u.x));
                    float2 f1 = __half22float2(*reinterpret_cast<__half2*>(&u.y));
                    acc.x += f0.x; acc.y += f0.y; acc.z += f1.x; acc.w += f1.y;
                }
            }
            for (; j < m; j++) {
                int c0 = g_csr[base + j];
                uint2 u = __ldg((const uint2*)(g_xh + (long long)c0 * D + lane * 4));
                float2 f0 = __half22float2(*reinterpret_cast<__half2*>(&u.x));
                float2 f1 = __half22float2(*reinterpret_cast<__half2*>(&u.y));
                acc.x += f0.x; acc.y += f0.y; acc.z += f1.x; acc.w += f1.y;
            }
            const float invd = 1.0f / (float)max(cnt, 1);
            uint2 o;
            o.x = packh2(acc.x * invd, acc.y * invd);
            o.y = packh2(acc.z * invd, acc.w * invd);
            *reinterpret_cast<uint2*>(aggA + nl * AP + lane * 4) = o;
        }
    };

    auto mma_product = [&](const __half* A, const uint32_t* B, float c[2][4][4]) {
#pragma unroll
        for (int kc = 0; kc < 8; kc++) {
            const int kb = kc * 16;
            const int kpb = kc * 8;
            uint32_t a[2][4];
#pragma unroll
            for (int mt = 0; mt < 2; mt++) {
                int r_ = arow + mt * 16;
                a[mt][0] = *(const uint32_t*)(A + (r_    ) * AP + kb + 2 * lk);
                a[mt][1] = *(const uint32_t*)(A + (r_ + 8) * AP + kb + 2 * lk);
                a[mt][2] = *(const uint32_t*)(A + (r_    ) * AP + kb + 2 * lk + 8);
                a[mt][3] = *(const uint32_t*)(A + (r_ + 8) * AP + kb + 2 * lk + 8);
            }
            uint32_t b[4][2];
#pragma unroll
            for (int nt = 0; nt < 4; nt++) {
                b[nt][0] = B[(kpb + lk    ) * BP + bn + nt * 8];
                b[nt][1] = B[(kpb + lk + 4) * BP + bn + nt * 8];
            }
#pragma unroll
            for (int mt = 0; mt < 2; mt++)
#pragma unroll
                for (int nt = 0; nt < 4; nt++) {
                    asm volatile(
                        "mma.sync.aligned.m16n8k16.row.col.f32.f16.f16.f32 "
                        "{%0,%1,%2,%3}, {%4,%5,%6,%7}, {%8,%9}, {%0,%1,%2,%3};"
                        : "+f"(c[mt][nt][0]), "+f"(c[mt][nt][1]),
                          "+f"(c[mt][nt][2]), "+f"(c[mt][nt][3])
                        : "r"(a[mt][0]), "r"(a[mt][1]), "r"(a[mt][2]), "r"(a[mt][3]),
                          "r"(b[nt][0]), "r"(b[nt][1]));
                }
        }
    };

    // ---- prologue: B + xA(t0) async; gather aggA(t0) synchronously ----
    for (int v = t; v < 2048; v += 512) {
        int kp = v >> 5;
        int c4 = (v & 31) << 2;
        cp16((char*)BR + kp * BP * 4 + c4 * 4, g_rp + kp * 128 + c4);
        cp16((char*)BW + kp * BP * 4 + c4 * 4, g_wp + kp * 128 + c4);
    }
    load_xA(blockIdx.x, 0);
    asm volatile("cp.async.commit_group;");
    gather_agg(blockIdx.x, 0);

    float2 bb[4];
#pragma unroll
    for (int nt = 0; nt < 4; nt++)
        bb[nt] = *reinterpret_cast<const float2*>(bias + wn * 32 + nt * 8 + lq * 2);

    int it = 0;
    for (int tile = blockIdx.x; tile < NT_TILES; tile += GRID_GEMM, it++) {
        const int bf = it & 1;
        const int next = tile + GRID_GEMM;
        const bool has_next = next < NT_TILES;

        if (has_next) {
            load_xA(next, bf ^ 1);
            asm volatile("cp.async.commit_group;");
            asm volatile("cp.async.wait_group 1;");
        } else {
            asm volatile("cp.async.wait_group 0;");
        }
        __syncthreads();   // xA(tile) + aggA(tile) visible to all warps

        float c[2][4][4];
#pragma unroll
        for (int mt = 0; mt < 2; mt++)
#pragma unroll
            for (int nt = 0; nt < 4; nt++)
#pragma unroll
                for (int e = 0; e < 4; e++) c[mt][nt][e] = 0.f;

        const __half* xA   = (const __half*)(smraw + XA_B(bf));
        const __half* aggA = (const __half*)(smraw + AGG_B(bf));
        const int row0 = tile * 128;

        // warp-parity interleave: overlap next-tile gather with current MMA
        if (wid & 1) {
            mma_product(xA, BR, c);
            mma_product(aggA, BW, c);
            if (has_next) gather_agg(next, bf ^ 1);
        } else {
            if (has_next) gather_agg(next, bf ^ 1);
            mma_product(xA, BR, c);
            mma_product(aggA, BW, c);
        }

        // epilogue
#pragma unroll
        for (int mt = 0; mt < 2; mt++) {
#pragma unroll
            for (int nt = 0; nt < 4; nt++) {
                int cb = wn * 32 + nt * 8 + lq * 2;
                int r0 = row0 + wm * 32 + mt * 16 + lr;
                if (r0 < N_NODES) {
                    float2 o = make_float2(c[mt][nt][0] + bb[nt].x, c[mt][nt][1] + bb[nt].y);
                    *reinterpret_cast<float2*>(out + (long long)r0 * D + cb) = o;
                }
                int r1 = r0 + 8;
                if (r1 < N_NODES) {
                    float2 o = make_float2(c[mt][nt][2] + bb[nt].x, c[mt][nt][3] + bb[nt].y);
                    *reinterpret_cast<float2*>(out + (long long)r1 * D + cb) = o;
                }
            }
        }
        __syncthreads();   // buffers bf (read) and bf^1 (gather-written) settled
    }
}

// ---------------------------------------------------------------------------
extern "C" void kernel_launch(void* const* d_in, const int* in_sizes, int n_in,
                              void* d_out, int out_size) {
    const float* x    = (const float*)d_in[0];
    const void*  ei   = d_in[1];
    const float* W    = (const float*)d_in[2];
    const float* R    = (const float*)d_in[3];
    const float* bias = (const float*)d_in[4];
    float*       out  = (float*)d_out;

    detect_zero_kernel<<<(N_NODES + 255) / 256, 256>>>((const int*)ei);
    prep_kernel<<<12501, 256>>>(x, W, R, ei);

    {
        cudaFuncSetAttribute(gemm_fused,
                             cudaFuncAttributeMaxDynamicSharedMemorySize, SM_BYTES);
        gemm_fused<<<GRID_GEMM, 512, SM_BYTES>>>(bias, out);
    }
}